// round 16
// baseline (speedup 1.0000x reference)
#include <cuda_runtime.h>

// Inverse Haar (db1) 2D wavelet step, grouped transposed conv stride2/kernel2.
// Input  x: (16, 128, 128, 128) f32  -> channel pairs (2g, 2g+1)
// Filters:  (2, 2, 2) f32
// Output:   (16, 64, 256, 256) f32
//
// out[b,g,2h+i,2w+j] = x[b,2g,h,w]*f0[i,j] + x[b,2g+1,h,w]*f1[i,j]
//
// FINAL (= R11, measured best 63.2us, DRAM 75.9% of spec / ~6.0 TB/s).
// 256-bit stores (st.global.cs.v8.f32, sm_100+): lane j loads input float4
// cols 4j..4j+3 from both channel planes (LDG.128, 512B dense/warp) and
// stores output cols 8j..8j+7 of rows 2h and 2h+1 (STG.256 -- one store
// instruction per warp covers a full contiguous 1KB output row). Both
// streams simultaneously fully warp-dense. Streaming-store hint keeps the
// write-once output from thrashing L2.
//
// Verified terminal across the search space: half-dense stores (R3, 105us),
// split STG.128 geometry (R5/R7, 63.6us), MLP=8 (R6, neutral), persistent
// grid (R8, regressed), L2 prefetch hint (R14, neutral). DRAM is the only
// binding resource at ~76% of spec -- the HBM mixed-stream ceiling for a
// mandatory 134MB-read + 268MB-write pattern.

#define HW_IN   (128 * 128)
#define HW_OUT  (256 * 256)
#define W_IN    128
#define W_OUT   256

__device__ __forceinline__ void stg256_cs(float* p, const float* v) {
    asm volatile(
        "st.global.cs.v8.f32 [%0], {%1, %2, %3, %4, %5, %6, %7, %8};"
        :: "l"(p),
           "f"(v[0]), "f"(v[1]), "f"(v[2]), "f"(v[3]),
           "f"(v[4]), "f"(v[5]), "f"(v[6]), "f"(v[7])
        : "memory");
}

__global__ __launch_bounds__(512) void iwt_kernel(
    const float* __restrict__ x,
    const float* __restrict__ f,
    float* __restrict__ out)
{
    int tid = blockIdx.x * blockDim.x + threadIdx.x;
    int j  = tid & 31;           // lane: input float4-chunk / output float8-chunk
    int h  = (tid >> 5) & 127;   // input row
    int bg = tid >> 12;          // b*64 + g in [0,1024)

    const float f00 = __ldg(f + 0), f01 = __ldg(f + 1);
    const float f10 = __ldg(f + 2), f11 = __ldg(f + 3);
    const float g00 = __ldg(f + 4), g01 = __ldg(f + 5);
    const float g10 = __ldg(f + 6), g11 = __ldg(f + 7);

    // Input: channel 2g at plane 2*bg, channel 2g+1 one plane later.
    int in_base = 2 * bg * HW_IN + h * W_IN;
    const float4* arow = reinterpret_cast<const float4*>(x + in_base);
    const float4* brow = reinterpret_cast<const float4*>(x + in_base + HW_IN);

    // Two dense LDG.128: each 512B contiguous per warp.
    float4 a = __ldg(arow + j);   // input cols 4j..4j+3, channel 2g
    float4 b = __ldg(brow + j);   // input cols 4j..4j+3, channel 2g+1

    // Output rows 2h, 2h+1; lane j writes cols 8j..8j+7 of each.
    int out_base = bg * HW_OUT + (h << 1) * W_OUT + (j << 3);

    float o0[8], o1[8];
    // input col c -> output cols 2c (filter col 0) and 2c+1 (filter col 1)
    o0[0] = fmaf(b.x, g00, a.x * f00);  o0[1] = fmaf(b.x, g01, a.x * f01);
    o0[2] = fmaf(b.y, g00, a.y * f00);  o0[3] = fmaf(b.y, g01, a.y * f01);
    o0[4] = fmaf(b.z, g00, a.z * f00);  o0[5] = fmaf(b.z, g01, a.z * f01);
    o0[6] = fmaf(b.w, g00, a.w * f00);  o0[7] = fmaf(b.w, g01, a.w * f01);

    o1[0] = fmaf(b.x, g10, a.x * f10);  o1[1] = fmaf(b.x, g11, a.x * f11);
    o1[2] = fmaf(b.y, g10, a.y * f10);  o1[3] = fmaf(b.y, g11, a.y * f11);
    o1[4] = fmaf(b.z, g10, a.z * f10);  o1[5] = fmaf(b.z, g11, a.z * f11);
    o1[6] = fmaf(b.w, g10, a.w * f10);  o1[7] = fmaf(b.w, g11, a.w * f11);

    // Two STG.256: each instruction = 1024B contiguous per warp (a full
    // 256-float output row).
    stg256_cs(out + out_base,         o0);
    stg256_cs(out + out_base + W_OUT, o1);
}

extern "C" void kernel_launch(void* const* d_in, const int* in_sizes, int n_in,
                              void* d_out, int out_size) {
    const float* x = (const float*)d_in[0];   // (16,128,128,128) f32
    const float* f = (const float*)d_in[1];   // (2,2,2) f32
    float* out = (float*)d_out;               // (16,64,256,256) f32

    const int total = 16 * 64 * 128 * 32;     // 4,194,304 threads
    const int tpb = 512;
    iwt_kernel<<<total / tpb, tpb>>>(x, f, out);
}

// round 17
// speedup vs baseline: 1.0020x; 1.0020x over previous
#include <cuda_runtime.h>

// Inverse Haar (db1) 2D wavelet step, grouped transposed conv stride2/kernel2.
// Input  x: (16, 128, 128, 128) f32  -> channel pairs (2g, 2g+1)
// Filters:  (2, 2, 2) f32
// Output:   (16, 64, 256, 256) f32
//
// out[b,g,2h+i,2w+j] = x[b,2g,h,w]*f0[i,j] + x[b,2g+1,h,w]*f1[i,j]
//
// R16 = R11 geometry (measured best: STG.256, both streams fully warp-dense,
// 63.2us / DRAM 75.9%) with DEFAULT-priority 256-bit stores (no .cs) -- the
// one untested qualifier. Rationale: .cs evict-first may drain dirty L2
// lines in smaller bursts; default priority lets contiguous dirty data from
// neighboring warps accumulate and sweep to DRAM in larger writes.
// All else byte-identical to R11.

#define HW_IN   (128 * 128)
#define HW_OUT  (256 * 256)
#define W_IN    128
#define W_OUT   256

__device__ __forceinline__ void stg256(float* p, const float* v) {
    asm volatile(
        "st.global.v8.f32 [%0], {%1, %2, %3, %4, %5, %6, %7, %8};"
        :: "l"(p),
           "f"(v[0]), "f"(v[1]), "f"(v[2]), "f"(v[3]),
           "f"(v[4]), "f"(v[5]), "f"(v[6]), "f"(v[7])
        : "memory");
}

__global__ __launch_bounds__(512) void iwt_kernel(
    const float* __restrict__ x,
    const float* __restrict__ f,
    float* __restrict__ out)
{
    int tid = blockIdx.x * blockDim.x + threadIdx.x;
    int j  = tid & 31;           // lane: input float4-chunk / output float8-chunk
    int h  = (tid >> 5) & 127;   // input row
    int bg = tid >> 12;          // b*64 + g in [0,1024)

    const float f00 = __ldg(f + 0), f01 = __ldg(f + 1);
    const float f10 = __ldg(f + 2), f11 = __ldg(f + 3);
    const float g00 = __ldg(f + 4), g01 = __ldg(f + 5);
    const float g10 = __ldg(f + 6), g11 = __ldg(f + 7);

    // Input: channel 2g at plane 2*bg, channel 2g+1 one plane later.
    int in_base = 2 * bg * HW_IN + h * W_IN;
    const float4* arow = reinterpret_cast<const float4*>(x + in_base);
    const float4* brow = reinterpret_cast<const float4*>(x + in_base + HW_IN);

    // Two dense LDG.128: each 512B contiguous per warp.
    float4 a = __ldg(arow + j);   // input cols 4j..4j+3, channel 2g
    float4 b = __ldg(brow + j);   // input cols 4j..4j+3, channel 2g+1

    // Output rows 2h, 2h+1; lane j writes cols 8j..8j+7 of each.
    int out_base = bg * HW_OUT + (h << 1) * W_OUT + (j << 3);

    float o0[8], o1[8];
    // input col c -> output cols 2c (filter col 0) and 2c+1 (filter col 1)
    o0[0] = fmaf(b.x, g00, a.x * f00);  o0[1] = fmaf(b.x, g01, a.x * f01);
    o0[2] = fmaf(b.y, g00, a.y * f00);  o0[3] = fmaf(b.y, g01, a.y * f01);
    o0[4] = fmaf(b.z, g00, a.z * f00);  o0[5] = fmaf(b.z, g01, a.z * f01);
    o0[6] = fmaf(b.w, g00, a.w * f00);  o0[7] = fmaf(b.w, g01, a.w * f01);

    o1[0] = fmaf(b.x, g10, a.x * f10);  o1[1] = fmaf(b.x, g11, a.x * f11);
    o1[2] = fmaf(b.y, g10, a.y * f10);  o1[3] = fmaf(b.y, g11, a.y * f11);
    o1[4] = fmaf(b.z, g10, a.z * f10);  o1[5] = fmaf(b.z, g11, a.z * f11);
    o1[6] = fmaf(b.w, g10, a.w * f10);  o1[7] = fmaf(b.w, g11, a.w * f11);

    // Two STG.256: each instruction = 1024B contiguous per warp (a full
    // 256-float output row).
    stg256(out + out_base,         o0);
    stg256(out + out_base + W_OUT, o1);
}

extern "C" void kernel_launch(void* const* d_in, const int* in_sizes, int n_in,
                              void* d_out, int out_size) {
    const float* x = (const float*)d_in[0];   // (16,128,128,128) f32
    const float* f = (const float*)d_in[1];   // (2,2,2) f32
    float* out = (float*)d_out;               // (16,64,256,256) f32

    const int total = 16 * 64 * 128 * 32;     // 4,194,304 threads
    const int tpb = 512;
    iwt_kernel<<<total / tpb, tpb>>>(x, f, out);
}